// round 16
// baseline (speedup 1.0000x reference)
#include <cuda_runtime.h>
#include <cuda_bf16.h>
#include <math.h>
#include <stdint.h>

typedef __nv_bfloat16 bf16;

#define Dq 1024
#define Pq 128
#define Bq 4096
#define Nq 8192
#define Cq 1000
#define Mall 20480              // 4096 + 2*8192

// ---------------- scratch (static device memory; no allocations) -----------
__device__ bf16  g_xb  [(size_t)Mall * Dq];
__device__ bf16  g_W1b [Pq * Dq];
__device__ bf16  g_W2b [Pq * Pq];
__device__ bf16  g_Wpb [Dq * Dq];
__device__ bf16  g_W3T [3 * Pq * Dq];        // [g][j][d] = W3[(3d+g)*128 + j]
__device__ bf16  g_H1b [(size_t)Mall * Pq];
__device__ bf16  g_H2b [(size_t)Mall * Pq];
__device__ bf16  g_Mt  [Pq * Pq];
__device__ float g_vb  [Pq];
__device__ bf16  g_Wvp [Dq * Pq];            // Wp @ W3v
__device__ float g_bv2 [Dq];                 // Wp b3v + bp
__device__ bf16  g_T   [Bq * Pq];
__device__ bf16  g_Ucat[(size_t)2 * Bq * Pq];
__device__ float g_Up  [(size_t)8 * Bq * Pq];      // [split*2+bank][row][dim]
__device__ float g_Um  [8 * Bq];
__device__ float g_Ul  [8 * Bq];
__device__ float g_MtP [8 * Pq * Pq];
__device__ float g_WvpP[4 * Dq * Pq];
__device__ float g_TP  [(size_t)4 * Bq * Pq];
__device__ float g_F   [(size_t)2 * Bq * Dq];
__device__ bf16  g_Ap  [(size_t)Bq * 3 * Dq];
__device__ bf16  g_Bp  [(size_t)Cq * 3 * Dq];

// ---------------- helpers ---------------------------------------------------
__device__ __forceinline__ uint32_t s2u(const void* p) {
    uint32_t a;
    asm("{ .reg .u64 t; cvta.to.shared.u64 t, %1; cvt.u32.u64 %0, t; }"
        : "=r"(a) : "l"(p));
    return a;
}
__device__ __forceinline__ void ldmx4(uint32_t* r, uint32_t a) {
    asm volatile("ldmatrix.sync.aligned.m8n8.x4.shared.b16 {%0,%1,%2,%3}, [%4];"
                 : "=r"(r[0]), "=r"(r[1]), "=r"(r[2]), "=r"(r[3]) : "r"(a));
}
__device__ __forceinline__ void ldmx4t(uint32_t* r, uint32_t a) {
    asm volatile("ldmatrix.sync.aligned.m8n8.x4.trans.shared.b16 {%0,%1,%2,%3}, [%4];"
                 : "=r"(r[0]), "=r"(r[1]), "=r"(r[2]), "=r"(r[3]) : "r"(a));
}
__device__ __forceinline__ void mma16816(float* c, const uint32_t* a, const uint32_t* b) {
    asm volatile("mma.sync.aligned.m16n8k16.row.col.f32.bf16.bf16.f32 "
                 "{%0,%1,%2,%3}, {%4,%5,%6,%7}, {%8,%9}, {%0,%1,%2,%3};"
                 : "+f"(c[0]), "+f"(c[1]), "+f"(c[2]), "+f"(c[3])
                 : "r"(a[0]), "r"(a[1]), "r"(a[2]), "r"(a[3]),
                   "r"(b[0]), "r"(b[1]));
}
__device__ __forceinline__ void cp16(uint32_t dst, const void* src) {
    asm volatile("cp.async.cg.shared.global [%0], [%1], 16;"
                 :: "r"(dst), "l"(src));
}
__device__ __forceinline__ void cp16z(uint32_t dst, const void* src, int sz) {
    asm volatile("cp.async.cg.shared.global [%0], [%1], 16, %2;"
                 :: "r"(dst), "l"(src), "r"(sz));
}
__device__ __forceinline__ void cp_commit() {
    asm volatile("cp.async.commit_group;" ::: "memory");
}
__device__ __forceinline__ uint32_t packbf2(float x, float y) {
    __nv_bfloat162 h = __floats2bfloat162_rn(x, y);
    return *reinterpret_cast<uint32_t*>(&h);
}

// ---------------- mma.sync GEMM ---------------------------------------------
#define SROW 80
#define ATILE_B (128 * SROW)
#define NSTAGE  3

#define MODE_SMUL   0
#define MODE_BNRELU 1
#define MODE_RESID  3
#define MODE_LS     4
#define MODE_BIAS   5
#define MODE_PART   6  // fp32 out (split-K partial)

template <int BN, bool TRANSB>
__device__ __forceinline__ void stage_load(const bf16* __restrict__ A,
                                           const bf16* __restrict__ Bm,
                                           int N_, int K_, int lda, int ldb,
                                           int m0, int n0, int k0,
                                           uint32_t sbase, int tid)
{
    const int T = 2 * BN;
#pragma unroll
    for (int i = tid; i < 512; i += T) {
        const int row = i >> 2, ch = i & 3;
        cp16(sbase + row * SROW + ch * 16,
             A + (size_t)(m0 + row) * lda + k0 + ch * 8);
    }
    if (TRANSB) {
#pragma unroll
        for (int i = tid; i < 4 * BN; i += T) {
            const int row = i >> 2, ch = i & 3;
            const int grow = n0 + row;
            const int v = (grow < N_);
            cp16z(sbase + ATILE_B + row * SROW + ch * 16,
                  Bm + (size_t)(v ? grow : 0) * ldb + k0 + ch * 8, v ? 16 : 0);
        }
    } else {
        constexpr int CPR = BN / 8;
        constexpr int BROW = 2 * BN + 16;
#pragma unroll
        for (int i = tid; i < 32 * CPR; i += T) {
            const int kk = i / CPR, ch = i % CPR;
            cp16(sbase + ATILE_B + kk * BROW + ch * 16,
                 Bm + (size_t)(k0 + kk) * N_ + n0 + ch * 8);
        }
    }
}

template <int BN, bool TRANSB>
__device__ __forceinline__ void compute_stage(uint32_t sbase, int lane,
                                              int wm, int wn,
                                              float acc[4][4][4])
{
    constexpr int BROW = 2 * BN + 16;
    const uint32_t aBase = sbase + (wm * 64 + (lane & 15)) * SROW + (lane >> 4) * 16;
    uint32_t bBase;
    if (TRANSB) {
        bBase = sbase + ATILE_B +
                (wn * 32 + ((lane >> 4) << 3) + (lane & 7)) * SROW +
                (((lane >> 3) & 1) << 4);
    } else {
        bBase = sbase + ATILE_B +
                ((lane & 7) + (((lane >> 3) & 1) << 3)) * BROW +
                (wn * 32 + (lane >> 4) * 8) * 2;
    }
#pragma unroll
    for (int kh = 0; kh < 2; ++kh) {
        uint32_t af[4][4];
#pragma unroll
        for (int tm = 0; tm < 4; ++tm)
            ldmx4(af[tm], aBase + tm * 16 * SROW + kh * 32);
        uint32_t bfr[4][2];
#pragma unroll
        for (int tp = 0; tp < 2; ++tp) {
            uint32_t r[4];
            if (TRANSB) ldmx4(r, bBase + tp * 16 * SROW + kh * 32);
            else        ldmx4t(r, bBase + kh * 16 * BROW + tp * 32);
            bfr[2 * tp][0] = r[0];  bfr[2 * tp][1] = r[1];
            bfr[2 * tp + 1][0] = r[2]; bfr[2 * tp + 1][1] = r[3];
        }
#pragma unroll
        for (int tm = 0; tm < 4; ++tm)
#pragma unroll
            for (int tn = 0; tn < 4; ++tn)
                mma16816(acc[tm][tn], af[tm], bfr[tn]);
    }
}

template <int BN, bool TRANSB>
__global__ __launch_bounds__(2 * BN)
void tc_gemm(const bf16* __restrict__ A, const bf16* __restrict__ Bm,
             int M, int N, int K, int lda, int ldb, int ldc, int kparts,
             size_t aOff1, size_t bOff1, size_t cOff1B,
             size_t aOff2, size_t bOff2, size_t cOff2B,
             int mode, float scale,
             const float* __restrict__ bias, const float* __restrict__ gam,
             const float* __restrict__ bet, const float* __restrict__ mean,
             const float* __restrict__ var, const float* __restrict__ resid,
             const float* __restrict__ lsp,
             void* __restrict__ Cout)
{
    constexpr int NW = BN / 32;
    constexpr int BSTAGE = TRANSB ? BN * SROW : 32 * (2 * BN + 16);
    constexpr int STAGE = ATILE_B + BSTAGE;
    extern __shared__ char smem[];
    const uint32_t sb = s2u(smem);
    {
        const int z = blockIdx.z;
        const int part = z % kparts, bank = z / kparts;
        A    += bank * aOff2 + part * aOff1;
        Bm   += bank * bOff2 + part * bOff1;
        Cout  = (void*)((char*)Cout + (size_t)bank * cOff2B + (size_t)part * cOff1B);
    }
    const int tid  = threadIdx.x;
    const int lane = tid & 31;
    const int wid  = tid >> 5;
    const int wm = wid / NW, wn = wid % NW;
    const int m0 = blockIdx.y * 128;
    const int n0 = blockIdx.x * BN;
    const int NC = K >> 5;

    float acc[4][4][4];
#pragma unroll
    for (int a = 0; a < 4; ++a)
#pragma unroll
        for (int b = 0; b < 4; ++b)
#pragma unroll
            for (int c = 0; c < 4; ++c) acc[a][b][c] = 0.f;

#pragma unroll
    for (int s = 0; s < 2; ++s) {
        stage_load<BN, TRANSB>(A, Bm, N, K, lda, ldb, m0, n0, s * 32, sb + s * STAGE, tid);
        cp_commit();
    }

    for (int i = 0; i < NC; ++i) {
        asm volatile("cp.async.wait_group 1;" ::: "memory");
        __syncthreads();
        compute_stage<BN, TRANSB>(sb + (i % NSTAGE) * STAGE, lane, wm, wn, acc);
        if (i + 2 < NC)
            stage_load<BN, TRANSB>(A, Bm, N, K, lda, ldb, m0, n0, (i + 2) * 32,
                                   sb + ((i + 2) % NSTAGE) * STAGE, tid);
        cp_commit();
    }
    asm volatile("cp.async.wait_group 0;" ::: "memory");

    const float lsv = (mode == MODE_LS) ? __expf(lsp[0]) : 1.f;

#pragma unroll
    for (int tm = 0; tm < 4; ++tm) {
#pragma unroll
        for (int tn = 0; tn < 4; ++tn) {
            const int r0 = m0 + wm * 64 + tm * 16 + (lane >> 2);
            const int c0 = n0 + wn * 32 + tn * 8 + 2 * (lane & 3);
#pragma unroll
            for (int h = 0; h < 2; ++h) {
                const int row = r0 + 8 * h;
                const float f0 = acc[tm][tn][2 * h];
                const float f1 = acc[tm][tn][2 * h + 1];
                if (mode == MODE_SMUL) {
                    __nv_bfloat162 p = __floats2bfloat162_rn(f0 * scale, f1 * scale);
                    *reinterpret_cast<__nv_bfloat162*>(
                        (bf16*)Cout + (size_t)row * ldc + c0) = p;
                } else if (mode == MODE_BIAS) {
                    __nv_bfloat162 p = __floats2bfloat162_rn(f0 + bias[c0],
                                                             f1 + bias[c0 + 1]);
                    *reinterpret_cast<__nv_bfloat162*>(
                        (bf16*)Cout + (size_t)row * ldc + c0) = p;
                } else if (mode == MODE_PART) {
                    float* Cf = (float*)Cout + (size_t)row * ldc + c0;
                    Cf[0] = f0; Cf[1] = f1;
                } else if (mode == MODE_BNRELU) {
                    float x0 = f0 + bias[c0];
                    x0 = (x0 - mean[c0]) * rsqrtf(var[c0] + 1e-5f) * gam[c0] + bet[c0];
                    float x1 = f1 + bias[c0 + 1];
                    x1 = (x1 - mean[c0 + 1]) * rsqrtf(var[c0 + 1] + 1e-5f) * gam[c0 + 1]
                         + bet[c0 + 1];
                    __nv_bfloat162 p = __floats2bfloat162_rn(fmaxf(x0, 0.f),
                                                             fmaxf(x1, 0.f));
                    *reinterpret_cast<__nv_bfloat162*>(
                        (bf16*)Cout + (size_t)row * ldc + c0) = p;
                } else if (mode == MODE_RESID) {
                    float* Cf = (float*)Cout + (size_t)row * ldc + c0;
                    const float2 rv = *reinterpret_cast<const float2*>(
                        resid + (size_t)(row & (Bq - 1)) * ldc + c0);
                    float2 o;
                    o.x = f0 + bias[c0] + rv.x;
                    o.y = f1 + bias[c0 + 1] + rv.y;
                    *reinterpret_cast<float2*>(Cf) = o;
                } else { // MODE_LS
                    if (c0 < N) {
                        float* Cf = (float*)Cout + (size_t)row * ldc + c0;
                        Cf[0] = f0 * lsv;
                        Cf[1] = f1 * lsv;
                    }
                }
            }
        }
    }
}

#define SMEM_NT128 (NSTAGE * (ATILE_B + 128 * SROW))
#define SMEM_NT256 (NSTAGE * (ATILE_B + 256 * SROW))
#define SMEM_NN256 (NSTAGE * (ATILE_B + 32 * (2 * 256 + 16)))

// ---------------- flash attention v2 ----------------------------------------
// U = softmax(0.1 T H2^T) @ H2. grid (32 qb, 2 banks, 4 splits), 256 thr.
// Per CTA: 128 q x 2048 keys, K-tiles of 64 rows. 2 CTAs/SM.
#define FL_RS   272
#define FLQ_B (128 * FL_RS)               // 34816
#define FLK_B (64 * FL_RS)                // 17408
#define FL_SMEM (FLQ_B + 2 * FLK_B)       // 69632

__global__ __launch_bounds__(256, 2)
void flash_kernel(const bf16* __restrict__ Tq, const bf16* __restrict__ H2k,
                  float* __restrict__ Up, float* __restrict__ Um,
                  float* __restrict__ Ul)
{
    extern __shared__ char smem[];
    const uint32_t sQ = s2u(smem);
    const uint32_t sK = sQ + FLQ_B;
    const int tid = threadIdx.x, lane = tid & 31, wid = tid >> 5;
    const int qb = blockIdx.x, bank = blockIdx.y, split = blockIdx.z;
    const bf16* Q  = Tq + (size_t)qb * 128 * Pq;
    const bf16* KB = H2k + ((size_t)bank * Nq + (size_t)split * 2048) * Pq;

    for (int i = tid; i < 2048; i += 256) {
        const int r = i >> 4, ch = i & 15;
        cp16(sQ + r * FL_RS + ch * 16, Q + (size_t)r * Pq + ch * 8);
    }
    cp_commit();
    for (int i = tid; i < 1024; i += 256) {
        const int r = i >> 4, ch = i & 15;
        cp16(sK + r * FL_RS + ch * 16, KB + (size_t)r * Pq + ch * 8);
    }
    cp_commit();

    float m[2] = {-3e38f, -3e38f}, l[2] = {0.f, 0.f};
    float Uacc[16][4];
#pragma unroll
    for (int n = 0; n < 16; ++n)
#pragma unroll
        for (int e = 0; e < 4; ++e) Uacc[n][e] = 0.f;

    const uint32_t aQ = sQ + (wid * 16 + (lane & 15)) * FL_RS + (lane >> 4) * 16;
    const uint32_t bS0 = (((lane >> 4) << 3) + (lane & 7)) * FL_RS +
                         (((lane >> 3) & 1) << 4);
    const uint32_t bU0 = ((lane & 7) + (((lane >> 3) & 1) << 3)) * FL_RS +
                         ((lane >> 4) << 4);

    for (int t = 0; t < 32; ++t) {
        asm volatile("cp.async.wait_group 0;" ::: "memory");
        __syncthreads();
        const uint32_t cur = sK + (t & 1) * FLK_B;
        if (t + 1 < 32) {
            const uint32_t nxt = sK + ((t + 1) & 1) * FLK_B;
            const bf16* src = KB + (size_t)(t + 1) * 64 * Pq;
            for (int i = tid; i < 1024; i += 256) {
                const int r = i >> 4, ch = i & 15;
                cp16(nxt + r * FL_RS + ch * 16, src + (size_t)r * Pq + ch * 8);
            }
        }
        cp_commit();

        // ---- S = Q @ K^T (16 q-rows x 64 keys per warp) ----
        float S[8][4];
#pragma unroll
        for (int n = 0; n < 8; ++n)
#pragma unroll
            for (int e = 0; e < 4; ++e) S[n][e] = 0.f;
#pragma unroll
        for (int kh = 0; kh < 8; ++kh) {
            uint32_t af[4];
            ldmx4(af, aQ + kh * 16);
#pragma unroll
            for (int tp = 0; tp < 4; ++tp) {
                uint32_t r[4];
                ldmx4(r, cur + bS0 + tp * 16 * FL_RS + kh * 16);
                uint32_t b0[2] = {r[0], r[1]}, b1[2] = {r[2], r[3]};
                mma16816(S[2 * tp], af, b0);
                mma16816(S[2 * tp + 1], af, b1);
            }
        }

        // ---- online softmax ----
#pragma unroll
        for (int h = 0; h < 2; ++h) {
            float tmax = -3e38f;
#pragma unroll
            for (int n = 0; n < 8; ++n)
                tmax = fmaxf(tmax, fmaxf(S[n][2 * h], S[n][2 * h + 1]));
            tmax = fmaxf(tmax, __shfl_xor_sync(0xffffffffu, tmax, 1));
            tmax = fmaxf(tmax, __shfl_xor_sync(0xffffffffu, tmax, 2));
            const float mn = fmaxf(m[h], 0.1f * tmax);
            const float alpha = __expf(m[h] - mn);
            float rs = 0.f;
#pragma unroll
            for (int n = 0; n < 8; ++n) {
#pragma unroll
                for (int e = 0; e < 2; ++e) {
                    const float p = __expf(0.1f * S[n][2 * h + e] - mn);
                    S[n][2 * h + e] = p;
                    rs += p;
                }
            }
            rs += __shfl_xor_sync(0xffffffffu, rs, 1);
            rs += __shfl_xor_sync(0xffffffffu, rs, 2);
            l[h] = l[h] * alpha + rs;
#pragma unroll
            for (int n = 0; n < 16; ++n) {
                Uacc[n][2 * h] *= alpha;
                Uacc[n][2 * h + 1] *= alpha;
            }
            m[h] = mn;
        }

        // ---- U += P @ K ----
#pragma unroll
        for (int ku = 0; ku < 4; ++ku) {
            uint32_t a[4];
            a[0] = packbf2(S[2 * ku][0], S[2 * ku][1]);
            a[1] = packbf2(S[2 * ku][2], S[2 * ku][3]);
            a[2] = packbf2(S[2 * ku + 1][0], S[2 * ku + 1][1]);
            a[3] = packbf2(S[2 * ku + 1][2], S[2 * ku + 1][3]);
#pragma unroll
            for (int tp = 0; tp < 8; ++tp) {
                uint32_t r[4];
                ldmx4t(r, cur + bU0 + ku * 16 * FL_RS + tp * 32);
                uint32_t b0[2] = {r[0], r[1]}, b1[2] = {r[2], r[3]};
                mma16816(Uacc[2 * tp], a, b0);
                mma16816(Uacc[2 * tp + 1], a, b1);
            }
        }
    }

    const size_t sbi = ((size_t)split * 2 + bank) * Bq;
    const int rowb = qb * 128 + wid * 16 + (lane >> 2);
#pragma unroll
    for (int h = 0; h < 2; ++h) {
        const int row = rowb + 8 * h;
        if ((lane & 3) == 0) { Um[sbi + row] = m[h]; Ul[sbi + row] = l[h]; }
#pragma unroll
        for (int n = 0; n < 16; ++n) {
            float2 v = make_float2(Uacc[n][2 * h], Uacc[n][2 * h + 1]);
            *reinterpret_cast<float2*>(
                Up + (sbi + row) * Pq + n * 8 + 2 * (lane & 3)) = v;
        }
    }
}

// merge 4 kv-splits
__global__ void combine_kernel(const float* __restrict__ Up,
                               const float* __restrict__ Um,
                               const float* __restrict__ Ul,
                               bf16* __restrict__ Ucat)
{
    const int row = blockIdx.x, bank = blockIdx.y, d = threadIdx.x;
    size_t idx[4];
    float mm[4];
    float mt = -3e38f;
#pragma unroll
    for (int s = 0; s < 4; ++s) {
        idx[s] = ((size_t)s * 2 + bank) * Bq + row;
        mm[s] = Um[idx[s]];
        mt = fmaxf(mt, mm[s]);
    }
    float den = 0.f, num = 0.f;
#pragma unroll
    for (int s = 0; s < 4; ++s) {
        const float a = __expf(mm[s] - mt);
        den += a * Ul[idx[s]];
        num += a * Up[idx[s] * Pq + d];
    }
    Ucat[((size_t)bank * Bq + row) * Pq + d] = __float2bfloat16(num / den);
}

// ---------------- small kernels --------------------------------------------
__global__ void cvt_all_kernel(const float* __restrict__ Fv,
                               const float* __restrict__ Fvs,
                               const float* __restrict__ Fvt,
                               const float* __restrict__ W1,
                               const float* __restrict__ W2,
                               const float* __restrict__ Wp,
                               const float* __restrict__ W3,
                               bf16* __restrict__ xb, bf16* __restrict__ W1b,
                               bf16* __restrict__ W2b, bf16* __restrict__ Wpb,
                               bf16* __restrict__ W3T)
{
    const int nXB = Mall * Dq;
    const int nW1 = Pq * Dq;
    const int nW2 = Pq * Pq;
    const int nWp = Dq * Dq;
    const int nT1 = Pq * Dq;
    int i = (blockIdx.x * blockDim.x + threadIdx.x) * 4;
    const float* src = nullptr;
    bf16* dst;
    float f4[4];
    bool gather = false;
    if (i < nXB) {
        if (i < Bq * Dq)                  { src = Fv + i;  }
        else if (i < (Bq + Nq) * Dq)      { src = Fvs + (i - Bq * Dq); }
        else                              { src = Fvt + (i - (Bq + Nq) * Dq); }
        dst = xb + i;
    } else if ((i -= nXB) < nW1)          { src = W1 + i; dst = W1b + i; }
    else if ((i -= nW1) < nW2)            { src = W2 + i; dst = W2b + i; }
    else if ((i -= nW2) < nWp)            { src = Wp + i; dst = Wpb + i; }
    else if ((i -= nWp) < 3 * nT1) {
        const int g = i / nT1;
        const int r = i - g * nT1;
        const int j = r >> 10, d0 = r & 1023;
#pragma unroll
        for (int e = 0; e < 4; ++e)
            f4[e] = W3[(3 * (d0 + e) + g) * 128 + j];
        dst = W3T + i;
        gather = true;
    } else return;
    if (!gather) {
        const float4 v = *reinterpret_cast<const float4*>(src);
        f4[0] = v.x; f4[1] = v.y; f4[2] = v.z; f4[3] = v.w;
    }
    __nv_bfloat162 a = __floats2bfloat162_rn(f4[0], f4[1]);
    __nv_bfloat162 b = __floats2bfloat162_rn(f4[2], f4[3]);
    uint2 pk;
    pk.x = *reinterpret_cast<uint32_t*>(&a);
    pk.y = *reinterpret_cast<uint32_t*>(&b);
    *reinterpret_cast<uint2*>(dst) = pk;
}

// block 4: vb[j]; blocks 0-3: bv2
__global__ void prep_misc_kernel(const float* __restrict__ W3,
                                 const float* __restrict__ b3,
                                 const float* __restrict__ Wp,
                                 const float* __restrict__ bp,
                                 float* __restrict__ vb,
                                 float* __restrict__ bv2)
{
    if (blockIdx.x == 4) {
        if (threadIdx.x >= 128) return;
        const int j = threadIdx.x;
        float acc = 0.f;
        for (int d = 0; d < 1024; ++d)
            acc += b3[3 * d] * W3[(3 * d + 1) * 128 + j];
        vb[j] = acc;
    } else {
        const int i = blockIdx.x * 256 + threadIdx.x;
        float acc = 0.f;
        const float* wpr = Wp + (size_t)i * 1024;
        for (int d = 0; d < 1024; ++d)
            acc += wpr[d] * b3[3 * d + 2];
        bv2[i] = acc + bp[i];
    }
}

// sum split-K partials -> bf16 (optional per-column bias, col = i % ldc)
__global__ void reduce_parts(const float* __restrict__ in, bf16* __restrict__ out,
                             int n, int parts, int stride,
                             const float* __restrict__ bias, int ldc)
{
    const int i = blockIdx.x * blockDim.x + threadIdx.x;
    if (i >= n) return;
    float s = 0.f;
    for (int p = 0; p < parts; ++p) s += in[(size_t)p * stride + i];
    if (bias) s += bias[i % ldc];
    out[i] = __float2bfloat16(s);
}

// G row = norm(F0)+norm(F1); write Ap = [Gh|Gh|Gl] directly
__global__ void norm2_build_Ap(const float* __restrict__ F, bf16* __restrict__ Ap)
{
    const float* p0 = F + (size_t)blockIdx.x * 1024;
    const float* p1 = p0 + (size_t)Bq * 1024;
    const int tid = threadIdx.x;
    const int lane = tid & 31, w = tid >> 5;

    const float4 v0 = *reinterpret_cast<const float4*>(p0 + tid * 4);
    const float4 v1 = *reinterpret_cast<const float4*>(p1 + tid * 4);
    float s0 = v0.x * v0.x + v0.y * v0.y + v0.z * v0.z + v0.w * v0.w;
    float s1 = v1.x * v1.x + v1.y * v1.y + v1.z * v1.z + v1.w * v1.w;
#pragma unroll
    for (int o = 16; o > 0; o >>= 1) {
        s0 += __shfl_xor_sync(0xffffffffu, s0, o);
        s1 += __shfl_xor_sync(0xffffffffu, s1, o);
    }
    __shared__ float sh0[8], sh1[8];
    if (lane == 0) { sh0[w] = s0; sh1[w] = s1; }
    __syncthreads();
    if (tid == 0) {
        float t0 = 0.f, t1 = 0.f;
#pragma unroll
        for (int i = 0; i < 8; ++i) { t0 += sh0[i]; t1 += sh1[i]; }
        sh0[0] = t0; sh1[0] = t1;
    }
    __syncthreads();
    const float rn0 = rsqrtf(sh0[0]);
    const float rn1 = rsqrtf(sh1[0]);

    float g[4];
    g[0] = v0.x * rn0 + v1.x * rn1;
    g[1] = v0.y * rn0 + v1.y * rn1;
    g[2] = v0.z * rn0 + v1.z * rn1;
    g[3] = v0.w * rn0 + v1.w * rn1;

    bf16* row = Ap + (size_t)blockIdx.x * 3072;
    const int c = tid * 4;
    uint32_t hi[2], lo[2];
#pragma unroll
    for (int q = 0; q < 2; ++q) {
        const float x = g[2 * q], y = g[2 * q + 1];
        const bf16 hx = __float2bfloat16(x), hy = __float2bfloat16(y);
        hi[q] = packbf2(x, y);
        __nv_bfloat162 hl = __floats2bfloat162_rn(x - __bfloat162float(hx),
                                                  y - __bfloat162float(hy));
        lo[q] = *reinterpret_cast<uint32_t*>(&hl);
    }
    *reinterpret_cast<uint2*>(row + c)        = make_uint2(hi[0], hi[1]);
    *reinterpret_cast<uint2*>(row + 1024 + c) = make_uint2(hi[0], hi[1]);
    *reinterpret_cast<uint2*>(row + 2048 + c) = make_uint2(lo[0], lo[1]);
}

// B' = [Fh | Fl | Fh]
__global__ void build_Bp_kernel(const float* __restrict__ Ft, bf16* __restrict__ Bp)
{
    const int idx = blockIdx.x * blockDim.x + threadIdx.x;
    if (idx >= Cq * Dq) return;
    const int r = idx >> 10, c = idx & 1023;
    const float v = Ft[idx];
    const bf16 h = __float2bfloat16(v);
    const bf16 l = __float2bfloat16(v - __bfloat162float(h));
    bf16* row = Bp + (size_t)r * 3072;
    row[c] = h; row[1024 + c] = l; row[2048 + c] = h;
}

// ---------------- host side ------------------------------------------------
struct GemmArgs {
    const float *bias = nullptr, *gam = nullptr, *bet = nullptr;
    const float *mean = nullptr, *var = nullptr, *resid = nullptr, *lsp = nullptr;
    int lda = 0, ldb = 0, ldc = 0;
    int kparts = 1, gz = 1;
    size_t aOff1 = 0, bOff1 = 0, cOff1B = 0;
    size_t aOff2 = 0, bOff2 = 0, cOff2B = 0;
};

static void tc(bool transB, const bf16* A, const bf16* B, int M, int N, int K,
               int mode, float scale, void* C, const GemmArgs& g)
{
    const int lda = g.lda ? g.lda : K;
    const int ldb = g.ldb ? g.ldb : K;
    const int ldc = g.ldc ? g.ldc : N;
    if (!transB) {
        dim3 grid(N / 256, M / 128, g.gz);
        tc_gemm<256, false><<<grid, 512, SMEM_NN256>>>(A, B, M, N, K, lda, ldb, ldc,
            g.kparts, g.aOff1, g.bOff1, g.cOff1B, g.aOff2, g.bOff2, g.cOff2B,
            mode, scale, g.bias, g.gam, g.bet, g.mean, g.var, g.resid, g.lsp, C);
    } else if (N >= 256) {
        dim3 grid((N + 255) / 256, M / 128, g.gz);
        tc_gemm<256, true><<<grid, 512, SMEM_NT256>>>(A, B, M, N, K, lda, ldb, ldc,
            g.kparts, g.aOff1, g.bOff1, g.cOff1B, g.aOff2, g.bOff2, g.cOff2B,
            mode, scale, g.bias, g.gam, g.bet, g.mean, g.var, g.resid, g.lsp, C);
    } else {
        dim3 grid((N + 127) / 128, M / 128, g.gz);
        tc_gemm<128, true><<<grid, 256, SMEM_NT128>>>(A, B, M, N, K, lda, ldb, ldc,
            g.kparts, g.aOff1, g.bOff1, g.cOff1B, g.aOff2, g.bOff2, g.cOff2B,
            mode, scale, g.bias, g.gam, g.bet, g.mean, g.var, g.resid, g.lsp, C);
    }
}

extern "C" void kernel_launch(void* const* d_in, const int* in_sizes, int n_in,
                              void* d_out, int out_size)
{
    (void)in_sizes; (void)n_in; (void)out_size;
    const float* Ft  = (const float*)d_in[0];
    const float* Fv  = (const float*)d_in[1];
    const float* Fvs = (const float*)d_in[2];
    const float* Fvt = (const float*)d_in[3];
    const float* W1  = (const float*)d_in[4];
    const float* b1  = (const float*)d_in[5];
    const float* g1  = (const float*)d_in[6];
    const float* be1 = (const float*)d_in[7];
    const float* m1  = (const float*)d_in[8];
    const float* v1  = (const float*)d_in[9];
    const float* W2  = (const float*)d_in[10];
    const float* b2  = (const float*)d_in[11];
    const float* g2  = (const float*)d_in[12];
    const float* be2 = (const float*)d_in[13];
    const float* m2  = (const float*)d_in[14];
    const float* v2  = (const float*)d_in[15];
    const float* W3  = (const float*)d_in[16];
    const float* b3  = (const float*)d_in[17];
    const float* Wp  = (const float*)d_in[18];
    const float* bp  = (const float*)d_in[19];
    const float* ls  = (const float*)d_in[20];
    float* out = (float*)d_out;

    cudaFuncSetAttribute((const void*)tc_gemm<128, true>,
                         cudaFuncAttributeMaxDynamicSharedMemorySize, SMEM_NT128);
    cudaFuncSetAttribute((const void*)tc_gemm<256, true>,
                         cudaFuncAttributeMaxDynamicSharedMemorySize, SMEM_NT256);
    cudaFuncSetAttribute((const void*)tc_gemm<256, false>,
                         cudaFuncAttributeMaxDynamicSharedMemorySize, SMEM_NN256);
    cudaFuncSetAttribute((const void*)flash_kernel,
                         cudaFuncAttributeMaxDynamicSharedMemorySize, FL_SMEM);

    bf16 *xb, *W1b, *W2b, *Wpb, *W3T, *H1b, *H2b, *Mt, *Wvp, *T, *Ucat, *Ap, *Bp;
    float *vb, *bv2, *F, *Up, *Um, *Ul, *MtP, *WvpP, *TP;
    cudaGetSymbolAddress((void**)&xb,   g_xb);
    cudaGetSymbolAddress((void**)&W1b,  g_W1b);
    cudaGetSymbolAddress((void**)&W2b,  g_W2b);
    cudaGetSymbolAddress((void**)&Wpb,  g_Wpb);
    cudaGetSymbolAddress((void**)&W3T,  g_W3T);
    cudaGetSymbolAddress((void**)&H1b,  g_H1b);
    cudaGetSymbolAddress((void**)&H2b,  g_H2b);
    cudaGetSymbolAddress((void**)&Mt,   g_Mt);
    cudaGetSymbolAddress((void**)&vb,   g_vb);
    cudaGetSymbolAddress((void**)&Wvp,  g_Wvp);
    cudaGetSymbolAddress((void**)&bv2,  g_bv2);
    cudaGetSymbolAddress((void**)&T,    g_T);
    cudaGetSymbolAddress((void**)&Ucat, g_Ucat);
    cudaGetSymbolAddress((void**)&Up,   g_Up);
    cudaGetSymbolAddress((void**)&Um,   g_Um);
    cudaGetSymbolAddress((void**)&Ul,   g_Ul);
    cudaGetSymbolAddress((void**)&MtP,  g_MtP);
    cudaGetSymbolAddress((void**)&WvpP, g_WvpP);
    cudaGetSymbolAddress((void**)&TP,   g_TP);
    cudaGetSymbolAddress((void**)&F,    g_F);
    cudaGetSymbolAddress((void**)&Ap,   g_Ap);
    cudaGetSymbolAddress((void**)&Bp,   g_Bp);

    // conversions + bias precomputes
    {
        const int total = Mall * Dq + Pq * Dq + Pq * Pq + Dq * Dq + 3 * Pq * Dq;
        cvt_all_kernel<<<(total / 4 + 255) / 256, 256>>>(
            Fv, Fvs, Fvt, W1, W2, Wp, W3, xb, W1b, W2b, Wpb, W3T);
    }
    prep_misc_kernel<<<5, 256>>>(W3, b3, Wp, bp, vb, bv2);

    // Mt = (W3q^T W3k)^T, split-K x8
    {
        GemmArgs a; a.lda = 1024; a.ldb = 1024; a.ldc = 128;
        a.kparts = 8; a.gz = 8;
        a.aOff1 = 128; a.bOff1 = 128; a.cOff1B = (size_t)128 * 128 * 4;
        tc(true, W3T + Pq * Dq, W3T, Pq, Pq, 128, MODE_PART, 1.f, MtP, a);
    }
    // Wvp = Wp @ W3v, split-K x4
    {
        GemmArgs a; a.lda = 1024; a.ldb = 1024; a.ldc = 128;
        a.kparts = 4; a.gz = 4;
        a.aOff1 = 256; a.bOff1 = 256; a.cOff1B = (size_t)1024 * 128 * 4;
        tc(true, Wpb, W3T + 2 * Pq * Dq, Dq, Pq, 256, MODE_PART, 1.f, WvpP, a);
    }
    reduce_parts<<<(16384 + 255) / 256, 256>>>(MtP, Mt, 16384, 8, 16384, nullptr, 1);
    reduce_parts<<<(131072 + 255) / 256, 256>>>(WvpP, Wvp, 131072, 4, 131072, nullptr, 1);

    // pre_project -> H2
    {
        GemmArgs a; a.bias = b1; a.gam = g1; a.bet = be1; a.mean = m1; a.var = v1;
        tc(true, xb, W1b, Mall, Pq, Dq, MODE_BNRELU, 1.f, H1b, a);
    }
    {
        GemmArgs a; a.bias = b2; a.gam = g2; a.bet = be2; a.mean = m2; a.var = v2;
        tc(true, H1b, W2b, Mall, Pq, Pq, MODE_BNRELU, 1.f, H2b, a);
    }

    // T = H2q @ Mt^T + v, split-K x4 (grid 1x32x4 = 128 CTAs)
    {
        GemmArgs a; a.lda = 128; a.ldb = 128; a.ldc = 128;
        a.kparts = 4; a.gz = 4;
        a.aOff1 = 32; a.bOff1 = 32; a.cOff1B = (size_t)Bq * Pq * 4;
        tc(true, H2b, Mt, Bq, Pq, 32, MODE_PART, 1.f, TP, a);
    }
    reduce_parts<<<(Bq * Pq + 255) / 256, 256>>>(TP, T, Bq * Pq, 4,
                                                 Bq * Pq, vb, 128);

    // flash attention (32 qb, 2 banks, 4 splits; 2 CTAs/SM)
    flash_kernel<<<dim3(Bq / 128, 2, 4), 256, FL_SMEM>>>(
        T, H2b + (size_t)Bq * Pq, Up, Um, Ul);
    combine_kernel<<<dim3(Bq, 2), 128>>>(Up, Um, Ul, Ucat);

    // F = Fv + Ucat @ Wvp^T + bv2 (per bank)
    {
        GemmArgs a; a.bias = bv2; a.resid = Fv;
        a.gz = 2;
        a.aOff2 = (size_t)Bq * Pq;
        a.cOff2B = (size_t)Bq * Dq * sizeof(float);
        tc(true, Ucat, Wvp, Bq, Dq, Pq, MODE_RESID, 1.f, F, a);
    }

    // normalize + build Ap, Bp, final GEMM
    norm2_build_Ap<<<Bq, 256>>>(F, Ap);
    build_Bp_kernel<<<(Cq * Dq + 255) / 256, 256>>>(Ft, Bp);
    {
        GemmArgs a; a.lsp = ls;
        tc(true, Ap, Bp, Bq, Cq, 3 * Dq, MODE_LS, 1.f, out, a);
    }
}